// round 12
// baseline (speedup 1.0000x reference)
#include <cuda_runtime.h>
#include <cstdint>

// Problem constants
#define B  4
#define C  64
#define H  256
#define W  256
#define HW (H*W)              // 65536
#define NPIX (B*HW)           // 262144 source pixels
#define NIMG (C*HW)           // 4194304 image elements

#define RGRID 1024            // reduce grid: 1024*256 threads * 4 float4 = NIMG

// Scratch image as float4 per (group, y, x): img4[g*HW + y*W + x] holds
// channels {4g..4g+3} of pixel (y,x). Warp lanes are consecutive x, so a
// warp's 32 float4 REDs to one corner land in few contiguous cache lines.
// __device__ globals are zero-initialized at load; the reduce re-zeroes
// everything it consumes, so every kernel_launch call sees clean state.
__device__ float4       g_image4[NIMG / 4];   // 16 MB
__device__ double       g_acc[2];             // [0]=sum, [1]=sumsq
__device__ unsigned int g_count;              // reduce block completion counter

// ---------------------------------------------------------------------------
// Kernel 1: forward bilinear splat.
// One thread per pixel, 16 groups of 4 channels. Displacement u*s_c is
// monotone in c and spans <1px, so per group the corner cell either is
// uniform (4 v4-REDs, ~93%) or shifts by one in exactly one axis: the union
// of both cells' corners is a 2x3 / 3x2 footprint = 6 cells -> 6 v4-REDs
// with per-cell merged payloads. Double-axis straddle (~0.1%): scalar.
// ---------------------------------------------------------------------------
__global__ void __launch_bounds__(256) splat_kernel(
    const float* __restrict__ flow,
    const float* __restrict__ spike)
{
    const int idx = blockIdx.x * blockDim.x + threadIdx.x;   // grid exact

    const int b = idx >> 16;          // / HW
    const int p = idx & (HW - 1);     // % HW
    const int y = p >> 8;             // / W
    const int x = p & (W - 1);        // % W

    const float u = flow[(size_t)b * 2 * HW + p];
    const float v = flow[(size_t)b * 2 * HW + HW + p];
    const float* sp = spike + (size_t)b * C * HW + p;

    const float xf = (float)x;
    const float yf = (float)y;

    #pragma unroll
    for (int g = 0; g < C / 4; ++g) {
        float w00[4], w10[4], w01[4], w11[4];
        int   x0[4], y0[4];

        #pragma unroll
        for (int k = 0; k < 4; ++k) {
            const int c = g * 4 + k;
            const float val = __ldg(sp + (size_t)c * HW);
            const float s  = ((float)c - 31.5f) * (1.0f / 64.0f);
            const float xn = fmaf(u, s, xf);
            const float yn = fmaf(v, s, yf);
            const float fx = floorf(xn);
            const float fy = floorf(yn);
            const float wx = xn - fx;
            const float wy = yn - fy;
            x0[k] = (int)fx;
            y0[k] = (int)fy;
            const float a  = val * wx;      // val*wx
            const float bb = val - a;       // val*(1-wx)
            const float q  = 1.0f - wy;
            w00[k] = bb * q;
            w10[k] = a  * q;
            w01[k] = bb * wy;
            w11[k] = a  * wy;
        }

        float4* plane = g_image4 + (size_t)g * HW;
        const int dx = x0[3] - x0[0];
        const int dy = y0[3] - y0[0];

        if ((dx == 0) & (dy == 0)) {
            // ---- fast path: whole group shares one corner cell ----
            const int X0 = x0[0], Y0 = y0[0];
            const bool vx0 = (X0 >= 0)  & (X0 < W);
            const bool vx1 = (X0 >= -1) & (X0 < W - 1);

            if (Y0 >= 0 && Y0 < H) {
                float4* row = plane + Y0 * W;
                if (vx0) atomicAdd(row + X0,     make_float4(w00[0], w00[1], w00[2], w00[3]));
                if (vx1) atomicAdd(row + X0 + 1, make_float4(w10[0], w10[1], w10[2], w10[3]));
            }
            if (Y0 >= -1 && Y0 < H - 1) {
                float4* row = plane + (Y0 + 1) * W;
                if (vx0) atomicAdd(row + X0,     make_float4(w01[0], w01[1], w01[2], w01[3]));
                if (vx1) atomicAdd(row + X0 + 1, make_float4(w11[0], w11[1], w11[2], w11[3]));
            }
        } else if ((dy == 0) & ((dx == 1) | (dx == -1))) {
            // ---- x-straddle: cells xa and xa+1, same row. Footprint 2x3. ----
            const int xa = (dx == 1) ? x0[0] : x0[3];
            const int Y0 = y0[0];

            float t0[4], t1[4], t2[4], b0[4], b1[4], b2[4];
            #pragma unroll
            for (int k = 0; k < 4; ++k) {
                const bool left = (x0[k] == xa);
                t0[k] = left ? w00[k] : 0.0f;
                t1[k] = left ? w10[k] : w00[k];
                t2[k] = left ? 0.0f   : w10[k];
                b0[k] = left ? w01[k] : 0.0f;
                b1[k] = left ? w11[k] : w01[k];
                b2[k] = left ? 0.0f   : w11[k];
            }

            const bool vc0 = (xa >= 0)  & (xa < W);
            const bool vc1 = (xa >= -1) & (xa < W - 1);
            const bool vc2 = (xa >= -2) & (xa < W - 2);

            if (Y0 >= 0 && Y0 < H) {
                float4* row = plane + Y0 * W;
                if (vc0) atomicAdd(row + xa,     make_float4(t0[0], t0[1], t0[2], t0[3]));
                if (vc1) atomicAdd(row + xa + 1, make_float4(t1[0], t1[1], t1[2], t1[3]));
                if (vc2) atomicAdd(row + xa + 2, make_float4(t2[0], t2[1], t2[2], t2[3]));
            }
            if (Y0 >= -1 && Y0 < H - 1) {
                float4* row = plane + (Y0 + 1) * W;
                if (vc0) atomicAdd(row + xa,     make_float4(b0[0], b0[1], b0[2], b0[3]));
                if (vc1) atomicAdd(row + xa + 1, make_float4(b1[0], b1[1], b1[2], b1[3]));
                if (vc2) atomicAdd(row + xa + 2, make_float4(b2[0], b2[1], b2[2], b2[3]));
            }
        } else if ((dx == 0) & ((dy == 1) | (dy == -1))) {
            // ---- y-straddle: cells ya and ya+1, same col. Footprint 3x2. ----
            const int ya = (dy == 1) ? y0[0] : y0[3];
            const int X0 = x0[0];

            float r0l[4], r0r[4], r1l[4], r1r[4], r2l[4], r2r[4];
            #pragma unroll
            for (int k = 0; k < 4; ++k) {
                const bool top = (y0[k] == ya);
                r0l[k] = top ? w00[k] : 0.0f;
                r0r[k] = top ? w10[k] : 0.0f;
                r1l[k] = top ? w01[k] : w00[k];
                r1r[k] = top ? w11[k] : w10[k];
                r2l[k] = top ? 0.0f   : w01[k];
                r2r[k] = top ? 0.0f   : w11[k];
            }

            const bool vx0 = (X0 >= 0)  & (X0 < W);
            const bool vx1 = (X0 >= -1) & (X0 < W - 1);

            if (ya >= 0 && ya < H) {
                float4* row = plane + ya * W;
                if (vx0) atomicAdd(row + X0,     make_float4(r0l[0], r0l[1], r0l[2], r0l[3]));
                if (vx1) atomicAdd(row + X0 + 1, make_float4(r0r[0], r0r[1], r0r[2], r0r[3]));
            }
            if (ya >= -1 && ya < H - 1) {
                float4* row = plane + (ya + 1) * W;
                if (vx0) atomicAdd(row + X0,     make_float4(r1l[0], r1l[1], r1l[2], r1l[3]));
                if (vx1) atomicAdd(row + X0 + 1, make_float4(r1r[0], r1r[1], r1r[2], r1r[3]));
            }
            if (ya >= -2 && ya < H - 2) {
                float4* row = plane + (ya + 2) * W;
                if (vx0) atomicAdd(row + X0,     make_float4(r2l[0], r2l[1], r2l[2], r2l[3]));
                if (vx1) atomicAdd(row + X0 + 1, make_float4(r2r[0], r2r[1], r2r[2], r2r[3]));
            }
        } else {
            // ---- double straddle (~0.1%): scalar per channel ----
            float* pf = reinterpret_cast<float*>(plane);
            #pragma unroll
            for (int k = 0; k < 4; ++k) {
                const int X0 = x0[k], Y0 = y0[k];
                const bool vx0 = (X0 >= 0)  & (X0 < W);
                const bool vx1 = (X0 >= -1) & (X0 < W - 1);
                if (Y0 >= 0 && Y0 < H) {
                    float* row = pf + (size_t)(Y0 * W) * 4 + k;
                    if (vx0) atomicAdd(row + (size_t)X0 * 4,       w00[k]);
                    if (vx1) atomicAdd(row + (size_t)(X0 + 1) * 4, w10[k]);
                }
                if (Y0 >= -1 && Y0 < H - 1) {
                    float* row = pf + (size_t)((Y0 + 1) * W) * 4 + k;
                    if (vx0) atomicAdd(row + (size_t)X0 * 4,       w01[k]);
                    if (vx1) atomicAdd(row + (size_t)(X0 + 1) * 4, w11[k]);
                }
            }
        }
    }
}

// ---------------------------------------------------------------------------
// Kernel 2: fused reduce + finalize.
// Each warp owns 4 consecutive 512B chunks; 4 independent coalesced float4
// loads per thread (MLP=4). fp32 partials (16 values/thread, O(1) magnitude)
// promoted to double at warp level. Re-zeroes the image for the next graph
// replay; globally-last block computes -var(ddof=1).
// ---------------------------------------------------------------------------
__global__ void __launch_bounds__(256) reduce_final_kernel(float* __restrict__ out) {
    const int lane = threadIdx.x & 31;
    const int gwarp = (blockIdx.x * 256 + threadIdx.x) >> 5;
    const int base = gwarp * 128 + lane;          // float4 index

    const float4 v0 = g_image4[base];
    const float4 v1 = g_image4[base + 32];
    const float4 v2 = g_image4[base + 64];
    const float4 v3 = g_image4[base + 96];

    const float4 z4 = make_float4(0.f, 0.f, 0.f, 0.f);
    g_image4[base]      = z4;                     // re-zero for next replay
    g_image4[base + 32] = z4;
    g_image4[base + 64] = z4;
    g_image4[base + 96] = z4;

    float fs  = ((v0.x + v0.y) + (v0.z + v0.w)) + ((v1.x + v1.y) + (v1.z + v1.w))
              + ((v2.x + v2.y) + (v2.z + v2.w)) + ((v3.x + v3.y) + (v3.z + v3.w));
    float fs2 = (fmaf(v0.x, v0.x, v0.y * v0.y) + fmaf(v0.z, v0.z, v0.w * v0.w))
              + (fmaf(v1.x, v1.x, v1.y * v1.y) + fmaf(v1.z, v1.z, v1.w * v1.w))
              + (fmaf(v2.x, v2.x, v2.y * v2.y) + fmaf(v2.z, v2.z, v2.w * v2.w))
              + (fmaf(v3.x, v3.x, v3.y * v3.y) + fmaf(v3.z, v3.z, v3.w * v3.w));

    double s  = (double)fs;
    double s2 = (double)fs2;

    #pragma unroll
    for (int o = 16; o > 0; o >>= 1) {
        s  += __shfl_down_sync(0xFFFFFFFFu, s,  o);
        s2 += __shfl_down_sync(0xFFFFFFFFu, s2, o);
    }
    __shared__ double sh[2][8];
    const int wid = threadIdx.x >> 5;
    if (lane == 0) { sh[0][wid] = s; sh[1][wid] = s2; }
    __syncthreads();

    __shared__ bool is_last;
    if (threadIdx.x == 0) {
        double bs = 0.0, bs2 = 0.0;
        #pragma unroll
        for (int w = 0; w < 8; ++w) { bs += sh[0][w]; bs2 += sh[1][w]; }
        atomicAdd(&g_acc[0], bs);
        atomicAdd(&g_acc[1], bs2);
        __threadfence();
        unsigned int t = atomicAdd(&g_count, 1u);
        is_last = (t == RGRID - 1);
    }
    __syncthreads();

    if (is_last && threadIdx.x == 0) {
        const double sum   = g_acc[0];
        const double sumsq = g_acc[1];
        const double Nd    = (double)NIMG;
        const double var   = (sumsq - sum * sum / Nd) / (Nd - 1.0);
        out[0] = (float)(-var);
        // reset for next replay
        g_acc[0] = 0.0;
        g_acc[1] = 0.0;
        g_count  = 0u;
    }
}

// ---------------------------------------------------------------------------
extern "C" void kernel_launch(void* const* d_in, const int* in_sizes, int n_in,
                              void* d_out, int out_size)
{
    const float* flow;
    const float* spike;
    if (in_sizes[0] == 2 * NPIX) {
        flow  = (const float*)d_in[0];
        spike = (const float*)d_in[1];
    } else {
        flow  = (const float*)d_in[1];
        spike = (const float*)d_in[0];
    }
    float* out = (float*)d_out;

    splat_kernel<<<NPIX / 256, 256>>>(flow, spike);
    reduce_final_kernel<<<RGRID, 256>>>(out);
}